// round 1
// baseline (speedup 1.0000x reference)
#include <cuda_runtime.h>

// Conv2D: x[4096,4096] (fp32) cross-correlated with w[15,15], valid padding,
// + bias[1] -> out[4082,4082].
//
// Strategy: FFMA-roofline tiled kernel.
//   - Block = 256 threads, output tile 128 (x) * 32 (y).
//   - Thread = 4x4 register-blocked outputs (3600 FMAs/thread).
//   - Input tile (46 x 142) staged in shared, pitch 144 floats so per-row
//     float4 LDS.128 reads are 16B-aligned and bank-conflict-free.
//   - Weights staged in shared; one 15-tap row cached in registers per ky.

#define HI 4096
#define WI 4096
#define KH 15
#define KW 15
#define OH (HI - KH + 1)   // 4082
#define OW (WI - KW + 1)   // 4082

#define TOX 128            // output tile width
#define TOY 32             // output tile height
#define RX  4              // outputs per thread, x
#define RY  4              // outputs per thread, y
#define NTHREADS 256

#define IN_ROWS (TOY + KH - 1)   // 46
#define IN_COLS (TOX + KW - 1)   // 142
#define PITCH   144              // padded row (floats); 576B, 16B-aligned rows

__global__ __launch_bounds__(NTHREADS)
void conv2d_ffma_kernel(const float* __restrict__ x,
                        const float* __restrict__ w,
                        const float* __restrict__ bias,
                        float* __restrict__ out)
{
    __shared__ float s_in[IN_ROWS][PITCH];
    __shared__ float s_w[KH * KW];

    const int tid = threadIdx.x;
    const int ox0 = blockIdx.x * TOX;
    const int oy0 = blockIdx.y * TOY;

    // ---- Stage weights ----
    if (tid < KH * KW) s_w[tid] = w[tid];

    // ---- Stage input tile (zero-fill out of bounds) ----
    #pragma unroll 4
    for (int i = tid; i < IN_ROWS * IN_COLS; i += NTHREADS) {
        const int r = i / IN_COLS;
        const int c = i - r * IN_COLS;
        const int gy = oy0 + r;
        const int gx = ox0 + c;
        float v = 0.0f;
        if (gy < HI && gx < WI) v = __ldg(&x[gy * WI + gx]);
        s_in[r][c] = v;
    }
    __syncthreads();

    const int tx = tid & 31;   // 0..31 -> x
    const int ty = tid >> 5;   // 0..7  -> y

    float acc[RY][RX];
    #pragma unroll
    for (int r = 0; r < RY; ++r)
        #pragma unroll
        for (int j = 0; j < RX; ++j)
            acc[r][j] = 0.0f;

    // ---- Main loop: ky rolled (I$-friendly), everything inside unrolled ----
    #pragma unroll 1
    for (int ky = 0; ky < KH; ++ky) {
        // Cache one weight row in registers (uniform-address broadcast LDS).
        float wr[KW];
        #pragma unroll
        for (int kx = 0; kx < KW; ++kx) wr[kx] = s_w[ky * KW + kx];

        #pragma unroll
        for (int r = 0; r < RY; ++r) {
            const float* rowp = &s_in[ty * RY + r + ky][tx * RX];
            // 18 needed inputs, loaded as 5 conflict-free float4s (20 floats).
            float in[20];
            #pragma unroll
            for (int q = 0; q < 5; ++q) {
                const float4 v = *reinterpret_cast<const float4*>(rowp + 4 * q);
                in[4 * q + 0] = v.x;
                in[4 * q + 1] = v.y;
                in[4 * q + 2] = v.z;
                in[4 * q + 3] = v.w;
            }
            #pragma unroll
            for (int kx = 0; kx < KW; ++kx)
                #pragma unroll
                for (int j = 0; j < RX; ++j)
                    acc[r][j] = fmaf(wr[kx], in[kx + j], acc[r][j]);
        }
    }

    // ---- Epilogue: bias + guarded stores ----
    const float b = __ldg(&bias[0]);
    #pragma unroll
    for (int r = 0; r < RY; ++r) {
        const int oy = oy0 + ty * RY + r;
        if (oy >= OH) continue;
        #pragma unroll
        for (int j = 0; j < RX; ++j) {
            const int ox = ox0 + tx * RX + j;
            if (ox < OW) out[(long)oy * OW + ox] = acc[r][j] + b;
        }
    }
}

extern "C" void kernel_launch(void* const* d_in, const int* in_sizes, int n_in,
                              void* d_out, int out_size)
{
    const float* x    = (const float*)d_in[0];
    const float* w    = (const float*)d_in[1];
    const float* bias = (const float*)d_in[2];
    float* out        = (float*)d_out;

    dim3 grid((OW + TOX - 1) / TOX,   // 32
              (OH + TOY - 1) / TOY);  // 128
    conv2d_ffma_kernel<<<grid, NTHREADS>>>(x, w, bias, out);
}